// round 1
// baseline (speedup 1.0000x reference)
#include <cuda_runtime.h>
#include <cstdint>

#define F_DIM 1024
#define R_DIM 64
#define S_DIM 4096
#define TILE 32
#define THREADS 256
#define FCH 128
#define NCH (F_DIM / FCH)

#define PT_STRIDE 132   /* 128 + 4 : per-r bank offset = 4 -> conflict-free */
#define W_STRIDE 68     /* 64 + 4  : per-f bank offset = 4 -> conflict-free */
#define H_FLOATS (TILE * F_DIM)         /* 32768 */
#define MAT_FLOATS (FCH * W_STRIDE)     /* 8704 >= 64*132 = 8448 */
#define C_OFF (H_FLOATS + MAT_FLOATS)
#define OLD_OFF (C_OFF + TILE * R_DIM)
#define SMEM_FLOATS (OLD_OFF + TILE)
#define SMEM_BYTES (SMEM_FLOATS * 4)    /* 174208 bytes */

// ---- device scratch (no allocation allowed) ----
__device__ float g_G[R_DIM * R_DIM];
__device__ float g_M[R_DIM * R_DIM];
__device__ float g_W[F_DIM * R_DIM];    // W = P * G^-1, row-major [f][r]
__device__ float g_Pt[R_DIM * F_DIM];   // P^T, row-major [r][f]

typedef unsigned long long u64;

__device__ __forceinline__ void fma2(u64 &d, u64 a, u64 b) {
    asm("fma.rn.f32x2 %0, %1, %2, %0;" : "+l"(d) : "l"(a), "l"(b));
}
__device__ __forceinline__ float lo2(u64 v) { return __uint_as_float((unsigned)v); }
__device__ __forceinline__ float hi2(u64 v) { return __uint_as_float((unsigned)(v >> 32)); }

// ============================================================
// K1a: Gram matrix G = P^T P   (64x64 dots of length 1024)
// ============================================================
__global__ void k_gram(const float* __restrict__ probe) {
    int i = blockIdx.x >> 6, j = blockIdx.x & 63;
    float s = 0.f;
    for (int f = threadIdx.x; f < F_DIM; f += blockDim.x)
        s = fmaf(probe[f * R_DIM + i], probe[f * R_DIM + j], s);
    for (int o = 16; o; o >>= 1) s += __shfl_xor_sync(0xffffffffu, s, o);
    __shared__ float red[8];
    if ((threadIdx.x & 31) == 0) red[threadIdx.x >> 5] = s;
    __syncthreads();
    if (threadIdx.x == 0) {
        float t = 0.f;
        for (int w = 0; w < 8; w++) t += red[w];
        g_G[i * R_DIM + j] = t;
    }
}

// ============================================================
// K1b: M = G^-1 via Gauss-Jordan (G SPD + diagonally dominant,
// no pivoting needed). One block, 64 threads, one row each.
// ============================================================
__global__ void k_inv() {
    __shared__ float A[R_DIM][2 * R_DIM + 1];
    int r = threadIdx.x;
    for (int j = 0; j < R_DIM; j++) A[r][j] = g_G[r * R_DIM + j];
    for (int j = 0; j < R_DIM; j++) A[r][R_DIM + j] = (r == j) ? 1.f : 0.f;
    __syncthreads();
    for (int k = 0; k < R_DIM; k++) {
        if (r == k) {
            float inv = 1.f / A[k][k];
            for (int j = 0; j < 2 * R_DIM; j++) A[k][j] *= inv;
        }
        __syncthreads();
        if (r != k) {
            float fct = A[r][k];
            for (int j = 0; j < 2 * R_DIM; j++)
                A[r][j] = fmaf(-fct, A[k][j], A[r][j]);
        }
        __syncthreads();
    }
    for (int j = 0; j < R_DIM; j++) g_M[r * R_DIM + j] = A[r][R_DIM + j];
}

// ============================================================
// K1c: W = P * M  and  Pt = P^T
// ============================================================
__global__ void k_w(const float* __restrict__ probe) {
    __shared__ float Ms[R_DIM * R_DIM];
    for (int i = threadIdx.x; i < R_DIM * R_DIM; i += blockDim.x) Ms[i] = g_M[i];
    __syncthreads();
    int f = blockIdx.x * blockDim.x + threadIdx.x;
    float p[R_DIM];
    #pragma unroll
    for (int k = 0; k < R_DIM; k++) p[k] = probe[f * R_DIM + k];
    for (int r2 = 0; r2 < R_DIM; r2++) {
        float acc = 0.f;
        #pragma unroll
        for (int k = 0; k < R_DIM; k++) acc = fmaf(p[k], Ms[k * R_DIM + r2], acc);
        g_W[f * R_DIM + r2] = acc;
    }
    #pragma unroll
    for (int r2 = 0; r2 < R_DIM; r2++) g_Pt[r2 * F_DIM + f] = p[r2];
}

// ============================================================
// K2: main fused kernel.
// 32 rows per block, 256 threads: thread = (row = t>>3, seg = t&7).
//   phase A: c[row][r] = sum_f h[row][f] * Pt[r][f]   (f32x2 over f)
//   phase B: h[row][f] -= sum_r c[row][r] * W[f][r]   (f32x2 over r)
//   then rescale by old_norm/new_norm; s==0 rows copy input verbatim.
// ============================================================
__global__ void __launch_bounds__(THREADS, 1)
k_main(const float* __restrict__ hs, float* __restrict__ out) {
    extern __shared__ float smem[];
    float* h_s    = smem;
    float* mat_s  = smem + H_FLOATS;
    float* c_s    = smem + C_OFF;
    float* oldsq_s = smem + OLD_OFF;

    const int t = threadIdx.x;
    const int row = t >> 3;
    const int seg = t & 7;
    const long long g0 = (long long)blockIdx.x * TILE;

    // ---- load h tile, accumulate old-norm^2 per row ----
    {
        const float4* hin = (const float4*)(hs + g0 * F_DIM);
        float4* hsr = (float4*)(h_s + row * F_DIM);
        float sq = 0.f;
        #pragma unroll
        for (int k = 0; k < 32; k++) {
            float4 v = hin[row * 256 + k * 8 + seg];
            hsr[k * 8 + seg] = v;
            sq = fmaf(v.x, v.x, sq); sq = fmaf(v.y, v.y, sq);
            sq = fmaf(v.z, v.z, sq); sq = fmaf(v.w, v.w, sq);
        }
        sq += __shfl_xor_sync(0xffffffffu, sq, 1);
        sq += __shfl_xor_sync(0xffffffffu, sq, 2);
        sq += __shfl_xor_sync(0xffffffffu, sq, 4);
        if (seg == 0) oldsq_s[row] = sq;
    }
    __syncthreads();

    // ---- Phase A: coefficients c = H * P ----
    {
        u64 acc[8];
        #pragma unroll
        for (int j = 0; j < 8; j++) acc[j] = 0ull;

        for (int ch = 0; ch < NCH; ch++) {
            // stage Pt chunk [64 r][128 f] -> mat_s[r*PT_STRIDE + f]
            #pragma unroll
            for (int i = 0; i < 8; i++) {
                int idx = t + THREADS * i;
                int r2 = idx >> 5;
                int fo = (idx & 31) << 2;
                float4 v = *(const float4*)(g_Pt + r2 * F_DIM + ch * FCH + fo);
                *(float4*)(mat_s + r2 * PT_STRIDE + fo) = v;
            }
            __syncthreads();

            const float* hr = h_s + row * F_DIM + ch * FCH;
            #pragma unroll 2
            for (int f = 0; f < FCH; f += 4) {
                ulonglong2 hv = *(const ulonglong2*)(hr + f);  // broadcast (8 lanes same row)
                ulonglong2 pv[8];
                #pragma unroll
                for (int j = 0; j < 8; j++)
                    pv[j] = *(const ulonglong2*)(mat_s + (seg + 8 * j) * PT_STRIDE + f);
                #pragma unroll
                for (int j = 0; j < 8; j++) fma2(acc[j], hv.x, pv[j].x);
                #pragma unroll
                for (int j = 0; j < 8; j++) fma2(acc[j], hv.y, pv[j].y);
            }
            __syncthreads();
        }
        #pragma unroll
        for (int j = 0; j < 8; j++)
            c_s[row * R_DIM + seg + 8 * j] = lo2(acc[j]) + hi2(acc[j]);
    }
    __syncthreads();

    // ---- Phase B: h -= W * c  (in place), accumulate new-norm^2 ----
    float newsq = 0.f;
    {
        u64 creg[32];
        const u64* cr = (const u64*)(c_s + row * R_DIM);
        #pragma unroll
        for (int i = 0; i < 32; i++) creg[i] = cr[i];

        for (int ch = 0; ch < NCH; ch++) {
            // stage W chunk [128 f][64 r] -> mat_s[f*W_STRIDE + r]
            #pragma unroll
            for (int i = 0; i < 8; i++) {
                int idx = t + THREADS * i;
                int j = idx >> 4;
                int ro = (idx & 15) << 2;
                float4 v = *(const float4*)(g_W + (long long)(ch * FCH + j) * R_DIM + ro);
                *(float4*)(mat_s + j * W_STRIDE + ro) = v;
            }
            __syncthreads();

            #pragma unroll 2
            for (int i = 0; i < 16; i++) {
                int j = i * 8 + seg;
                const ulonglong2* wr = (const ulonglong2*)(mat_s + j * W_STRIDE);
                u64 a0 = 0ull, a1 = 0ull, a2 = 0ull, a3 = 0ull;
                #pragma unroll
                for (int q = 0; q < 16; q += 2) {
                    ulonglong2 w0 = wr[q];
                    ulonglong2 w1 = wr[q + 1];
                    fma2(a0, creg[2 * q],     w0.x);
                    fma2(a1, creg[2 * q + 1], w0.y);
                    fma2(a2, creg[2 * q + 2], w1.x);
                    fma2(a3, creg[2 * q + 3], w1.y);
                }
                float proj = (lo2(a0) + hi2(a0)) + (lo2(a1) + hi2(a1))
                           + (lo2(a2) + hi2(a2)) + (lo2(a3) + hi2(a3));
                int fi = row * F_DIM + ch * FCH + j;
                float o = h_s[fi] - proj;
                h_s[fi] = o;
                newsq = fmaf(o, o, newsq);
            }
            __syncthreads();
        }
    }

    // ---- per-row scale = old_norm / new_norm ----
    newsq += __shfl_xor_sync(0xffffffffu, newsq, 1);
    newsq += __shfl_xor_sync(0xffffffffu, newsq, 2);
    newsq += __shfl_xor_sync(0xffffffffu, newsq, 4);
    float scale = sqrtf(oldsq_s[row] / newsq);

    // ---- store (s==0 rows: copy original input) ----
    {
        long long grow = g0 + row;
        bool first = ((grow & (S_DIM - 1)) == 0);
        float4* orow = (float4*)(out + grow * F_DIM);
        if (!first) {
            const float4* hsr = (const float4*)(h_s + row * F_DIM);
            #pragma unroll
            for (int k = 0; k < 32; k++) {
                float4 v = hsr[k * 8 + seg];
                v.x *= scale; v.y *= scale; v.z *= scale; v.w *= scale;
                orow[k * 8 + seg] = v;
            }
        } else {
            const float4* irow = (const float4*)(hs + grow * F_DIM);
            #pragma unroll
            for (int k = 0; k < 32; k++) orow[k * 8 + seg] = irow[k * 8 + seg];
        }
    }
}

extern "C" void kernel_launch(void* const* d_in, const int* in_sizes, int n_in,
                              void* d_out, int out_size) {
    const float* hs = (const float*)d_in[0];
    const float* probe = (const float*)d_in[1];
    float* out = (float*)d_out;

    // precompute projector factors (tiny)
    k_gram<<<R_DIM * R_DIM, 256>>>(probe);
    k_inv<<<1, R_DIM>>>();
    k_w<<<F_DIM / 256, 256>>>(probe);

    // main fused pass
    cudaFuncSetAttribute(k_main, cudaFuncAttributeMaxDynamicSharedMemorySize, SMEM_BYTES);
    int rows = in_sizes[0] / F_DIM;        // 32768
    k_main<<<rows / TILE, THREADS, SMEM_BYTES>>>(hs, out);
}